// round 13
// baseline (speedup 1.0000x reference)
#include <cuda_runtime.h>
#include <math.h>

// RotationalConv2D: B=4,H=W=128,C=16,F=32,K=5 -> Ho=Wo=124
// Thread = one patch, owns all 32 output features (16 f32x2 acc pairs).
// Rotate in registers -> FFMA2 immediately. W served from smem with
// WARP-UNIFORM addresses -> broadcast LDS.128 (1 wavefront each), staged in
// 5-position chunks, double-buffered, prefetched during compute.
// (R12 bug fixed: W read offset cb*640 ull2, matching the 2560-float chunk.)

#define FMA2(acc, a, b) asm("fma.rn.f32x2 %0, %1, %2, %0;" : "+l"(acc) : "l"(a), "l"(b))
#define MUL2(d, a, b)   asm("mul.rn.f32x2 %0, %1, %2;" : "=l"(d) : "l"(a), "l"(b))
#define SPLAT(p, w)     asm("mov.b64 %0, {%1, %1};" : "=l"(p) : "r"(w))
#define UNPACK(lo, hi, p) asm("mov.b64 {%0, %1}, %2;" : "=r"(lo), "=r"(hi) : "l"(p))

#define NTHREADS 128
#define ITX 20              // tile 16 wide + 4
#define NCELL 240           // 20 x 12 cells
// smem floats: planes4 3840 | chsum 240 | W double buffer 2*2560
#define SM_W 4080
#define SMEM_FLOATS (4080 + 5120)   // 9200 floats = 36800 B

__device__ float WkT[12800];        // staging: [k][f], k = pos*16 + c

__global__ void prepW_kernel(const float* __restrict__ Wg) {
    int i = blockIdx.x * 256 + threadIdx.x;
    if (i < 12800) {
        int k = i >> 5, f = i & 31;
        WkT[k * 32 + f] = Wg[f * 400 + k];
    }
}

union F4U2 { float4 f4; ulonglong2 u2; };

__global__ __launch_bounds__(NTHREADS)
void rotconv_kernel(const float* __restrict__ in,
                    const float* __restrict__ bias,
                    float* __restrict__ out)
{
    extern __shared__ float smem[];
    float4* planes4 = (float4*)smem;                 // [c4*240 + cell]
    float*  chsum   = smem + 3840;
    float4* Wst4    = (float4*)(smem + SM_W);        // staging as float4
    const ulonglong2* Wst2 = (const ulonglong2*)(smem + SM_W);

    const int tid   = threadIdx.x;
    const int mr    = tid >> 4;     // 0..7
    const int mc    = tid & 15;     // 0..15
    const int tileX = blockIdx.x;   // 0..7  (16 wide)
    const int tileY = blockIdx.y;   // 0..15 (8 tall)
    const int img   = blockIdx.z;

    // ---------- Phase 0: load input tile (20x12 cells) + W chunk 0 ----------
    {
        const float4* in4 = (const float4*)in;
        #pragma unroll 1
        for (int cell = tid; cell < NCELL; cell += NTHREADS) {
            int y = cell / ITX;
            int x = cell - y * ITX;
            int gr = tileY * 8 + y;  if (gr > 127) gr = 127;
            int gc = tileX * 16 + x; if (gc > 127) gc = 127;
            const float4* src = in4 + ((img * 128 + gr) * 128 + gc) * 4;
            #pragma unroll
            for (int c4 = 0; c4 < 4; ++c4)
                planes4[c4 * NCELL + cell] = src[c4];
        }
        const float4* Wg4 = (const float4*)WkT;
        #pragma unroll
        for (int j = 0; j < 5; ++j)                  // chunk 0: 640 float4
            Wst4[j * NTHREADS + tid] = Wg4[j * NTHREADS + tid];
    }
    __syncthreads();

    // ---------- Phase 1: per-cell channel sums ----------
    #pragma unroll 1
    for (int cell = tid; cell < NCELL; cell += NTHREADS) {
        float4 a = planes4[cell], b = planes4[NCELL + cell],
               c = planes4[2 * NCELL + cell], d = planes4[3 * NCELL + cell];
        chsum[cell] = (a.x + a.y + a.z + a.w) + (b.x + b.y + b.z + b.w)
                    + (c.x + c.y + c.z + c.w) + (d.x + d.y + d.z + d.w);
    }
    __syncthreads();

    // ---------- Phase 2: centroid -> angle (own patch) ----------
    float co, si;
    {
        float tot = 0.f, sr = 0.f, sc = 0.f;
        #pragma unroll
        for (int yy = 0; yy < 5; ++yy)
            #pragma unroll
            for (int xx = 0; xx < 5; ++xx) {
                float s = chsum[(mr + yy) * ITX + (mc + xx)];
                tot += s; sr += s * (float)yy; sc += s * (float)xx;
            }
        tot += 1e-7f;
        float cr = sr / tot - 2.0f;
        float cc = sc / tot - 2.0f + 1e-7f;
        sincosf(atan2f(cr, cc), &si, &co);
    }

    const float scale = 1.0f / (1.0f + 1e-7f);
    const float xoff = (4.0f - (co * 4.0f - si * 4.0f)) * 0.5f;
    const float yoff = (4.0f - (si * 4.0f + co * 4.0f)) * 0.5f;

    unsigned long long acc[16];     // acc[fp] = {f(2fp), f(2fp+1)}
    #pragma unroll
    for (int j = 0; j < 16; ++j) acc[j] = 0ULL;

    // ---------- Phase 3: 5 chunks x 5 positions ----------
    #pragma unroll 1
    for (int ch = 0; ch < 5; ++ch) {
        const int cb = ch & 1;

        // prefetch next chunk into the other buffer (safe: that buffer's
        // readers finished at the barrier ending chunk ch-1)
        if (ch < 4) {
            const float4* Wg4 = (const float4*)WkT;
            const int nb = (ch + 1) & 1;
            #pragma unroll
            for (int j = 0; j < 5; ++j)
                Wst4[nb * 640 + j * NTHREADS + tid] =
                    Wg4[(ch + 1) * 640 + j * NTHREADS + tid];
        }

        #pragma unroll 1
        for (int lp = 0; lp < 5; ++lp) {
            const int pos = ch * 5 + lp;
            const int gy = pos / 5;
            const int gx = pos - gy * 5;

            float sx = (co * (float)gx - si * (float)gy + xoff) * scale;
            float sy = (si * (float)gx + co * (float)gy + yoff) * scale;
            float x0f = floorf(sx), y0f = floorf(sy);
            float wx = sx - x0f, wy = sy - y0f;
            int x0 = (int)x0f, y0 = (int)y0f;
            int x1 = x0 + 1,   y1 = y0 + 1;
            bool vx0 = (x0 >= 0) && (x0 < 5);
            bool vx1 = (x1 >= 0) && (x1 < 5);
            bool vy0 = (y0 >= 0) && (y0 < 5);
            bool vy1 = (y1 >= 0) && (y1 < 5);
            int x0c = x0 < 0 ? 0 : (x0 > 4 ? 4 : x0);
            int x1c = x1 < 0 ? 0 : (x1 > 4 ? 4 : x1);
            int y0c = y0 < 0 ? 0 : (y0 > 4 ? 4 : y0);
            int y1c = y1 < 0 ? 0 : (y1 > 4 ? 4 : y1);
            float w00 = (vx0 && vy0) ? (1.f - wx) * (1.f - wy) : 0.f;
            float w01 = (vx1 && vy0) ? wx * (1.f - wy)         : 0.f;
            float w10 = (vx0 && vy1) ? (1.f - wx) * wy         : 0.f;
            float w11 = (vx1 && vy1) ? wx * wy                 : 0.f;

            unsigned long long s00, s01, s10, s11;
            SPLAT(s00, __float_as_uint(w00));
            SPLAT(s01, __float_as_uint(w01));
            SPLAT(s10, __float_as_uint(w10));
            SPLAT(s11, __float_as_uint(w11));

            const int cell00 = (mr + y0c) * ITX + (mc + x0c);
            const int cell01 = (mr + y0c) * ITX + (mc + x1c);
            const int cell10 = (mr + y1c) * ITX + (mc + x0c);
            const int cell11 = (mr + y1c) * ITX + (mc + x1c);

            // W pairs for this position: warp-uniform smem reads (broadcast).
            // Units: ulonglong2 (16B). chunk = 640, position = 128, quad = 32.
            const ulonglong2* Wrow = Wst2 + cb * 640 + lp * 128;

            #pragma unroll
            for (int q = 0; q < 4; ++q) {               // channel quad
                const float4* pl = planes4 + q * NCELL;
                F4U2 a, b, c, d;
                a.f4 = pl[cell00];
                b.f4 = pl[cell01];
                c.f4 = pl[cell10];
                d.f4 = pl[cell11];

                unsigned long long r01, r23;            // rotated ch pairs
                MUL2(r01, a.u2.x, s00);
                FMA2(r01, b.u2.x, s01);
                FMA2(r01, c.u2.x, s10);
                FMA2(r01, d.u2.x, s11);
                MUL2(r23, a.u2.y, s00);
                FMA2(r23, b.u2.y, s01);
                FMA2(r23, c.u2.y, s10);
                FMA2(r23, d.u2.y, s11);

                unsigned v0, v1, v2, v3;
                UNPACK(v0, v1, r01);
                UNPACK(v2, v3, r23);
                unsigned long long sv;
                const ulonglong2* Wq = Wrow + q * 32;

                SPLAT(sv, v0);
                #pragma unroll
                for (int j = 0; j < 8; ++j) {
                    ulonglong2 wp = Wq[j];
                    FMA2(acc[2 * j],     sv, wp.x);
                    FMA2(acc[2 * j + 1], sv, wp.y);
                }
                SPLAT(sv, v1);
                #pragma unroll
                for (int j = 0; j < 8; ++j) {
                    ulonglong2 wp = Wq[8 + j];
                    FMA2(acc[2 * j],     sv, wp.x);
                    FMA2(acc[2 * j + 1], sv, wp.y);
                }
                SPLAT(sv, v2);
                #pragma unroll
                for (int j = 0; j < 8; ++j) {
                    ulonglong2 wp = Wq[16 + j];
                    FMA2(acc[2 * j],     sv, wp.x);
                    FMA2(acc[2 * j + 1], sv, wp.y);
                }
                SPLAT(sv, v3);
                #pragma unroll
                for (int j = 0; j < 8; ++j) {
                    ulonglong2 wp = Wq[24 + j];
                    FMA2(acc[2 * j],     sv, wp.x);
                    FMA2(acc[2 * j + 1], sv, wp.y);
                }
            }
        }
        __syncthreads();   // all warps done reading buffer cb; next chunk may
                           // overwrite it during chunk ch+1's prefetch
    }

    // ---------- Phase 4: write out (own patch, 32 f) ----------
    {
        const int oh = tileY * 8 + mr;
        const int ow = tileX * 16 + mc;
        if (oh < 124 && ow < 124) {
            float4* ob = (float4*)(out + ((size_t)((img * 124 + oh) * 124 + ow)) * 32);
            const float4* b4 = (const float4*)bias;
            union { unsigned long long u; float2 f; } p0, p1;
            #pragma unroll
            for (int j = 0; j < 8; ++j) {
                float4 bv = b4[j];
                p0.u = acc[2 * j];
                p1.u = acc[2 * j + 1];
                ob[j] = make_float4(p0.f.x + bv.x, p0.f.y + bv.y,
                                    p1.f.x + bv.z, p1.f.y + bv.w);
            }
        }
    }
}

extern "C" void kernel_launch(void* const* d_in, const int* in_sizes, int n_in,
                              void* d_out, int out_size)
{
    const float* in   = (const float*)d_in[0];   // [4,128,128,16]
    const float* Wg   = (const float*)d_in[1];   // [32,5,5,16]
    const float* bias = (const float*)d_in[2];   // [32]
    float* out = (float*)d_out;                  // [4,124,124,32]

    prepW_kernel<<<50, 256>>>(Wg);

    const int smem_bytes = SMEM_FLOATS * (int)sizeof(float);   // 36800
    cudaFuncSetAttribute(rotconv_kernel,
                         cudaFuncAttributeMaxDynamicSharedMemorySize, smem_bytes);
    dim3 grid(8, 16, 4);
    rotconv_kernel<<<grid, NTHREADS, smem_bytes>>>(in, bias, out);
}

// round 14
// speedup vs baseline: 1.3304x; 1.3304x over previous
#include <cuda_runtime.h>
#include <math.h>

// RotationalConv2D: B=4,H=W=128,C=16,F=32,K=5 -> Ho=Wo=124
// Thread = TWO patches (rows r and r+4, same column), owns all 32 features
// for both (2 x 16 f32x2 acc pairs). Rotate in registers -> FFMA2 directly.
// W in __constant__ ([k][f] pairs); every LDC.128 feeds 4 FFMA2 (2 patches),
// halving constant-port pressure vs R11. Block = 32 threads = 8x8 patch tile,
// grid 16x16x4 = 1024 blocks (one balanced wave).

#define FMA2(acc, a, b) asm("fma.rn.f32x2 %0, %1, %2, %0;" : "+l"(acc) : "l"(a), "l"(b))
#define MUL2(d, a, b)   asm("mul.rn.f32x2 %0, %1, %2;" : "=l"(d) : "l"(a), "l"(b))
#define SPLAT(p, w)     asm("mov.b64 %0, {%1, %1};" : "=l"(p) : "r"(w))
#define UNPACK(lo, hi, p) asm("mov.b64 {%0, %1}, %2;" : "=r"(lo), "=r"(hi) : "l"(p))

#define NTHREADS 32
#define ITX 12              // tile 8 + 4
#define NCELL 144           // 12 x 12 cells
// smem floats: planes4 4*144*4 = 2304 | chsum 144
#define SMEM_FLOATS 2448    // 9792 B

__constant__ ulonglong2 Wc2[3200];   // [k=400][8 pairs {f2j,f2j+1}]

__device__ float WkT[12800];         // staging: [k][f], k = pos*16 + c

__global__ void prepW_kernel(const float* __restrict__ Wg) {
    int i = blockIdx.x * 256 + threadIdx.x;
    if (i < 12800) {
        int k = i >> 5, f = i & 31;
        WkT[k * 32 + f] = Wg[f * 400 + k];
    }
}

union F4U2 { float4 f4; ulonglong2 u2; };

// bilinear setup for one patch -> 4 splatted weights + 4 cell indices
struct Bil {
    unsigned long long s00, s01, s10, s11;
    int c00, c01, c10, c11;
};

__device__ __forceinline__ Bil bil_setup(float co, float si, float xoff, float yoff,
                                         int gx, int gy, int mr, int mc) {
    const float scale = 1.0f / (1.0f + 1e-7f);
    float sx = (co * (float)gx - si * (float)gy + xoff) * scale;
    float sy = (si * (float)gx + co * (float)gy + yoff) * scale;
    float x0f = floorf(sx), y0f = floorf(sy);
    float wx = sx - x0f, wy = sy - y0f;
    int x0 = (int)x0f, y0 = (int)y0f;
    int x1 = x0 + 1,   y1 = y0 + 1;
    bool vx0 = (x0 >= 0) && (x0 < 5);
    bool vx1 = (x1 >= 0) && (x1 < 5);
    bool vy0 = (y0 >= 0) && (y0 < 5);
    bool vy1 = (y1 >= 0) && (y1 < 5);
    int x0c = x0 < 0 ? 0 : (x0 > 4 ? 4 : x0);
    int x1c = x1 < 0 ? 0 : (x1 > 4 ? 4 : x1);
    int y0c = y0 < 0 ? 0 : (y0 > 4 ? 4 : y0);
    int y1c = y1 < 0 ? 0 : (y1 > 4 ? 4 : y1);
    float w00 = (vx0 && vy0) ? (1.f - wx) * (1.f - wy) : 0.f;
    float w01 = (vx1 && vy0) ? wx * (1.f - wy)         : 0.f;
    float w10 = (vx0 && vy1) ? (1.f - wx) * wy         : 0.f;
    float w11 = (vx1 && vy1) ? wx * wy                 : 0.f;
    Bil b;
    SPLAT(b.s00, __float_as_uint(w00));
    SPLAT(b.s01, __float_as_uint(w01));
    SPLAT(b.s10, __float_as_uint(w10));
    SPLAT(b.s11, __float_as_uint(w11));
    b.c00 = (mr + y0c) * ITX + (mc + x0c);
    b.c01 = (mr + y0c) * ITX + (mc + x1c);
    b.c10 = (mr + y1c) * ITX + (mc + x0c);
    b.c11 = (mr + y1c) * ITX + (mc + x1c);
    return b;
}

__global__ __launch_bounds__(NTHREADS)
void rotconv_kernel(const float* __restrict__ in,
                    const float* __restrict__ bias,
                    float* __restrict__ out)
{
    extern __shared__ float smem[];
    float4* planes4 = (float4*)smem;        // [c4*144 + cell]
    float*  chsum   = smem + 2304;

    const int tid   = threadIdx.x;
    const int mrA   = tid >> 3;     // 0..3  (patch A row)
    const int mc    = tid & 7;      // 0..7
    const int mrB   = mrA + 4;      // patch B row
    const int tileX = blockIdx.x;   // 0..15
    const int tileY = blockIdx.y;   // 0..15
    const int img   = blockIdx.z;

    // ---------- Phase 0: load input tile (12x12 cells), plane-major ----------
    {
        const float4* in4 = (const float4*)in;
        #pragma unroll 1
        for (int cell = tid; cell < NCELL; cell += NTHREADS) {
            int y = cell / ITX;
            int x = cell - y * ITX;
            int gr = tileY * 8 + y; if (gr > 127) gr = 127;
            int gc = tileX * 8 + x; if (gc > 127) gc = 127;
            const float4* src = in4 + ((img * 128 + gr) * 128 + gc) * 4;
            #pragma unroll
            for (int c4 = 0; c4 < 4; ++c4)
                planes4[c4 * NCELL + cell] = src[c4];
        }
    }
    __syncthreads();

    // ---------- Phase 1: per-cell channel sums ----------
    #pragma unroll 1
    for (int cell = tid; cell < NCELL; cell += NTHREADS) {
        float4 a = planes4[cell], b = planes4[NCELL + cell],
               c = planes4[2 * NCELL + cell], d = planes4[3 * NCELL + cell];
        chsum[cell] = (a.x + a.y + a.z + a.w) + (b.x + b.y + b.z + b.w)
                    + (c.x + c.y + c.z + c.w) + (d.x + d.y + d.z + d.w);
    }
    __syncthreads();

    // ---------- Phase 2: centroid -> angle for both patches ----------
    float coA, siA, coB, siB;
    {
        float totA = 0.f, srA = 0.f, scA = 0.f;
        float totB = 0.f, srB = 0.f, scB = 0.f;
        #pragma unroll
        for (int yy = 0; yy < 5; ++yy)
            #pragma unroll
            for (int xx = 0; xx < 5; ++xx) {
                float sA = chsum[(mrA + yy) * ITX + (mc + xx)];
                float sB = chsum[(mrB + yy) * ITX + (mc + xx)];
                totA += sA; srA += sA * (float)yy; scA += sA * (float)xx;
                totB += sB; srB += sB * (float)yy; scB += sB * (float)xx;
            }
        totA += 1e-7f;
        totB += 1e-7f;
        sincosf(atan2f(srA / totA - 2.0f, scA / totA - 2.0f + 1e-7f), &siA, &coA);
        sincosf(atan2f(srB / totB - 2.0f, scB / totB - 2.0f + 1e-7f), &siB, &coB);
    }
    const float xoffA = (4.0f - (coA * 4.0f - siA * 4.0f)) * 0.5f;
    const float yoffA = (4.0f - (siA * 4.0f + coA * 4.0f)) * 0.5f;
    const float xoffB = (4.0f - (coB * 4.0f - siB * 4.0f)) * 0.5f;
    const float yoffB = (4.0f - (siB * 4.0f + coB * 4.0f)) * 0.5f;

    unsigned long long accA[16], accB[16];
    #pragma unroll
    for (int j = 0; j < 16; ++j) { accA[j] = 0ULL; accB[j] = 0ULL; }

    // ---------- Phase 3: 25 positions, register-resident, W from constant ----
    #pragma unroll 1
    for (int pos = 0; pos < 25; ++pos) {
        const int gy = pos / 5;
        const int gx = pos - gy * 5;

        Bil bA = bil_setup(coA, siA, xoffA, yoffA, gx, gy, mrA, mc);
        Bil bB = bil_setup(coB, siB, xoffB, yoffB, gx, gy, mrB, mc);

        const ulonglong2* Wrow = Wc2 + pos * 128;

        #pragma unroll
        for (int q = 0; q < 4; ++q) {               // channel quad
            const float4* pl = planes4 + q * NCELL;

            F4U2 a, b, c, d;
            a.f4 = pl[bA.c00]; b.f4 = pl[bA.c01];
            c.f4 = pl[bA.c10]; d.f4 = pl[bA.c11];
            unsigned long long rA01, rA23;
            MUL2(rA01, a.u2.x, bA.s00);
            FMA2(rA01, b.u2.x, bA.s01);
            FMA2(rA01, c.u2.x, bA.s10);
            FMA2(rA01, d.u2.x, bA.s11);
            MUL2(rA23, a.u2.y, bA.s00);
            FMA2(rA23, b.u2.y, bA.s01);
            FMA2(rA23, c.u2.y, bA.s10);
            FMA2(rA23, d.u2.y, bA.s11);

            a.f4 = pl[bB.c00]; b.f4 = pl[bB.c01];
            c.f4 = pl[bB.c10]; d.f4 = pl[bB.c11];
            unsigned long long rB01, rB23;
            MUL2(rB01, a.u2.x, bB.s00);
            FMA2(rB01, b.u2.x, bB.s01);
            FMA2(rB01, c.u2.x, bB.s10);
            FMA2(rB01, d.u2.x, bB.s11);
            MUL2(rB23, a.u2.y, bB.s00);
            FMA2(rB23, b.u2.y, bB.s01);
            FMA2(rB23, c.u2.y, bB.s10);
            FMA2(rB23, d.u2.y, bB.s11);

            unsigned vA[4], vB[4];
            UNPACK(vA[0], vA[1], rA01);
            UNPACK(vA[2], vA[3], rA23);
            UNPACK(vB[0], vB[1], rB01);
            UNPACK(vB[2], vB[3], rB23);

            const ulonglong2* Wq = Wrow + q * 32;
            #pragma unroll
            for (int t = 0; t < 4; ++t) {           // channel scalar in quad
                unsigned long long svA, svB;
                SPLAT(svA, vA[t]);
                SPLAT(svB, vB[t]);
                #pragma unroll
                for (int j = 0; j < 8; ++j) {       // f-pair quads
                    ulonglong2 wp = Wq[t * 8 + j];
                    FMA2(accA[2 * j],     svA, wp.x);
                    FMA2(accA[2 * j + 1], svA, wp.y);
                    FMA2(accB[2 * j],     svB, wp.x);
                    FMA2(accB[2 * j + 1], svB, wp.y);
                }
            }
        }
    }

    // ---------- Phase 4: write out both patches ----------
    {
        const float4* b4 = (const float4*)bias;
        union { unsigned long long u; float2 f; } p0, p1;
        const int ow = tileX * 8 + mc;
        if (ow < 124) {
            int ohA = tileY * 8 + mrA;
            if (ohA < 124) {
                float4* ob = (float4*)(out + ((size_t)((img * 124 + ohA) * 124 + ow)) * 32);
                #pragma unroll
                for (int j = 0; j < 8; ++j) {
                    float4 bv = b4[j];
                    p0.u = accA[2 * j];
                    p1.u = accA[2 * j + 1];
                    ob[j] = make_float4(p0.f.x + bv.x, p0.f.y + bv.y,
                                        p1.f.x + bv.z, p1.f.y + bv.w);
                }
            }
            int ohB = tileY * 8 + mrB;
            if (ohB < 124) {
                float4* ob = (float4*)(out + ((size_t)((img * 124 + ohB) * 124 + ow)) * 32);
                #pragma unroll
                for (int j = 0; j < 8; ++j) {
                    float4 bv = b4[j];
                    p0.u = accB[2 * j];
                    p1.u = accB[2 * j + 1];
                    ob[j] = make_float4(p0.f.x + bv.x, p0.f.y + bv.y,
                                        p1.f.x + bv.z, p1.f.y + bv.w);
                }
            }
        }
    }
}

extern "C" void kernel_launch(void* const* d_in, const int* in_sizes, int n_in,
                              void* d_out, int out_size)
{
    const float* in   = (const float*)d_in[0];   // [4,128,128,16]
    const float* Wg   = (const float*)d_in[1];   // [32,5,5,16]
    const float* bias = (const float*)d_in[2];   // [32]
    float* out = (float*)d_out;                  // [4,124,124,32]

    prepW_kernel<<<50, 256>>>(Wg);

    void* wsrc = nullptr;
    cudaGetSymbolAddress(&wsrc, WkT);
    cudaMemcpyToSymbolAsync(Wc2, wsrc, 12800 * sizeof(float), 0,
                            cudaMemcpyDeviceToDevice, 0);

    const int smem_bytes = SMEM_FLOATS * (int)sizeof(float);   // 9792
    cudaFuncSetAttribute(rotconv_kernel,
                         cudaFuncAttributeMaxDynamicSharedMemorySize, smem_bytes);
    dim3 grid(16, 16, 4);
    rotconv_kernel<<<grid, NTHREADS, smem_bytes>>>(in, bias, out);
}